// round 11
// baseline (speedup 1.0000x reference)
#include <cuda_runtime.h>

#define N_NODES 12288
#define FDIM    32

// Scratch. Zero-initialized at module load; k_final re-zeros what it consumed,
// so every launch starts clean (graph-replay safe). g_inv / g_ya are rewritten
// with identical values each launch, so no zeroing needed.
// NOTE: g_deg holds raw degree after k_front, then d = rsqrt(deg+1) after k_dinv.
__device__ __align__(16) float g_deg [N_NODES];
__device__            int   g_inv [N_NODES];          // node -> perm idx + 1 (0 = absent)
__device__ __align__(16) float g_ya  [N_NODES];       // raw atte scatter
__device__ __align__(16) float g_acc [N_NODES * FDIM];
__device__ __align__(16) float g_accA[N_NODES];

// ---------------------------------------------------------------------------
// K_front: fused independent work.
//   blocks [0, EB):     deg[r] += attr[e], 2 edges/thread (int2+float2 loads)
//   blocks [EB, EB+SB): inverse-perm table + attention-coefficient scatter
__global__ void k_front(const int* __restrict__ ei_row,
                        const float* __restrict__ attr, int nE,
                        const int* __restrict__ perm,
                        const float* __restrict__ coffe,
                        const int* __restrict__ bs_ptr,
                        int n_perm, int coffe_len, int EB) {
    if (blockIdx.x < EB) {
        int v = blockIdx.x * blockDim.x + threadIdx.x;   // pair index
        int e = v * 2;
        if (e + 1 < nE) {
            int2   r2 = ((const int2*)ei_row)[v];
            float2 a2 = ((const float2*)attr)[v];
            atomicAdd(&g_deg[r2.x], a2.x);
            atomicAdd(&g_deg[r2.y], a2.y);
        } else if (e < nE) {
            atomicAdd(&g_deg[ei_row[e]], attr[e]);
        }
    } else {
        int k = (blockIdx.x - EB) * blockDim.x + threadIdx.x;
        if (k < n_perm) {
            int node = perm[k];
            g_inv[node] = k + 1;
            int bs        = *bs_ptr;
            int node_num  = coffe_len / bs;     // 192
            int per_batch = n_perm / bs;        // win*node_num
            int b = k / per_batch;
            int n = k % node_num;
            g_ya[node] = coffe[b * node_num + n];
        }
    }
}

// ---------------------------------------------------------------------------
// K_dinv: convert raw degree -> d = rsqrt(deg+1) in place. ONE MUFU per node
// (vs. one per active edge-thread if computed inside k_edge: ~1.6M MUFU,
// ~11us of MUFU serialization chip-wide).
__global__ void k_dinv() {
    int i = blockIdx.x * blockDim.x + threadIdx.x;
    if (i < N_NODES) g_deg[i] = rsqrtf(g_deg[i] + 1.0f);
}

// ---------------------------------------------------------------------------
// K_edge: 8 threads per edge. Gather through the inverse-perm table: columns
// not in perm contribute exactly zero and are skipped (no feature load, no red).
//   acc[r, 4q:4q+4] += attr * d[c] * fea[inv[c]-1, 4q:4q+4]
__global__ void k_edge(const int* __restrict__ ei_row,
                       const int* __restrict__ ei_col,
                       const float* __restrict__ attr,
                       const float* __restrict__ fea, int nE) {
    int t = blockIdx.x * blockDim.x + threadIdx.x;
    int e = t >> 3;
    int q = t & 7;
    if (e >= nE) return;
    int c  = ei_col[e];
    int pk = g_inv[c];
    if (pk == 0) return;                        // column absent -> zero row

    int   r = ei_row[e];
    float s = attr[e] * g_deg[c];               // attr * d[c]  (g_deg holds d)

    float4 v = ((const float4*)(fea + (size_t)(pk - 1) * FDIM))[q];
    v.x *= s; v.y *= s; v.z *= s; v.w *= s;

    float* dst = g_acc + (size_t)r * FDIM + q * 4;
    asm volatile("red.global.add.v4.f32 [%0], {%1, %2, %3, %4};"
                 :: "l"(dst), "f"(v.x), "f"(v.y), "f"(v.z), "f"(v.w)
                 : "memory");

    if (q == 0) {
        atomicAdd(&g_accA[r], s * g_ya[c]);
    }
}

// ---------------------------------------------------------------------------
// K_final: x[i] = d[i]*(acc[i] + d[i]*x_zero[i])  (self-loop folded in);
//          atte[i] = d[i]*(accA[i] + d[i]*ya[i]).
// x_zero row fetched through inv (zero if absent). Re-zeros consumed scratch.
__global__ void k_final(const float* __restrict__ fea, float* __restrict__ out) {
    int t = blockIdx.x * blockDim.x + threadIdx.x;
    int i = t >> 3;
    int q = t & 7;
    if (i >= N_NODES) return;
    float di = g_deg[i];                         // g_deg holds d
    int   pk = g_inv[i];

    float4 y = make_float4(0.f, 0.f, 0.f, 0.f);
    if (pk) y = ((const float4*)(fea + (size_t)(pk - 1) * FDIM))[q];

    float4 acc = ((const float4*)(g_acc + (size_t)i * FDIM))[q];
    float4 o;
    o.x = di * fmaf(di, y.x, acc.x);
    o.y = di * fmaf(di, y.y, acc.y);
    o.z = di * fmaf(di, y.z, acc.z);
    o.w = di * fmaf(di, y.w, acc.w);
    ((float4*)out)[(size_t)i * (FDIM / 4) + q] = o;

    ((float4*)(g_acc + (size_t)i * FDIM))[q] = make_float4(0.f, 0.f, 0.f, 0.f);

    if (q == 0) {
        float ya = pk ? g_ya[i] : 0.f;
        out[(size_t)N_NODES * FDIM + i] = di * fmaf(di, ya, g_accA[i]);
        g_accA[i] = 0.f;
        g_deg[i]  = 0.f;
    }
}

// ---------------------------------------------------------------------------
extern "C" void kernel_launch(void* const* d_in, const int* in_sizes, int n_in,
                              void* d_out, int out_size) {
    // metadata order:
    // 0: fea float32[6144,32]  1: perm int32[6144]  2: edge_index int32[2,393216]
    // 3: edge_attr float32[393216]  4: node_atte float32[1536]
    // 5: all_node_num int32[1]  6: batch_size int32[1]
    const float* fea    = (const float*)d_in[0];
    const int*   perm   = (const int*)  d_in[1];
    const int*   eidx   = (const int*)  d_in[2];
    const float* attr   = (const float*)d_in[3];
    const float* coffe  = (const float*)d_in[4];
    const int*   bs_ptr = (const int*)  d_in[6];

    const int n_perm    = in_sizes[1];
    const int nE        = in_sizes[3];
    const int coffe_len = in_sizes[4];
    const int* ei_row = eidx;
    const int* ei_col = eidx + nE;

    float* out = (float*)d_out;
    (void)out_size; (void)n_in;

    const int T = 256;
    const int nV = (nE + 1) / 2;                     // 2 edges per thread
    const int EB = (nV + T - 1) / T;                 // edge-degree blocks
    const int SB = (n_perm + T - 1) / T;             // perm-scatter blocks

    k_front<<<EB + SB, T>>>(ei_row, attr, nE, perm, coffe, bs_ptr,
                            n_perm, coffe_len, EB);

    k_dinv<<<(N_NODES + T - 1) / T, T>>>();

    {
        long long nt = (long long)nE * 8;
        k_edge<<<(unsigned)((nt + T - 1) / T), T>>>(ei_row, ei_col, attr, fea, nE);
    }

    k_final<<<(N_NODES * 8 + T - 1) / T, T>>>(fea, out);
}